// round 3
// baseline (speedup 1.0000x reference)
#include <cuda_runtime.h>
#include <cstdint>

#define LDK 132                      // padded row pitch in floats (conflict-free, 16B-aligned rows)
#define TILE_B (128 * LDK * 4)       // 67584 bytes per 128x128 fp32 tile

#define SM_X   0
#define SM_Y0  TILE_B
#define SM_Y1  (2 * TILE_B)
#define SMEM_TOTAL (3 * TILE_B)

__device__ float g_norms[2 * 16 * 2048];   // [0,32768): ||x_row||^2, [32768,65536): ||y_row||^2

__device__ __forceinline__ uint32_t smem_u32(const void* p) {
    uint32_t a;
    asm("{ .reg .u64 t; cvta.to.shared.u64 t, %1; cvt.u32.u64 %0, t; }" : "=r"(a) : "l"(p));
    return a;
}
__device__ __forceinline__ void cp_async16(uint32_t dst, const float* src) {
    asm volatile("cp.async.cg.shared.global [%0], [%1], 16;" :: "r"(dst), "l"(src));
}
__device__ __forceinline__ void cp_commit() {
    asm volatile("cp.async.commit_group;" ::: "memory");
}
template <int N>
__device__ __forceinline__ void cp_wait() {
    asm volatile("cp.async.wait_group %0;" :: "n"(N) : "memory");
}
__device__ __forceinline__ void ldm_x4(uint32_t* r, uint32_t addr) {
    asm volatile("ldmatrix.sync.aligned.m8n8.x4.shared.b16 {%0,%1,%2,%3}, [%4];"
                 : "=r"(r[0]), "=r"(r[1]), "=r"(r[2]), "=r"(r[3]) : "r"(addr));
}
__device__ __forceinline__ void mma_tf32(float* c, const uint32_t* a, uint32_t b0, uint32_t b1) {
    asm volatile(
        "mma.sync.aligned.m16n8k8.row.col.f32.tf32.tf32.f32 "
        "{%0,%1,%2,%3},{%4,%5,%6,%7},{%8,%9},{%0,%1,%2,%3};"
        : "+f"(c[0]), "+f"(c[1]), "+f"(c[2]), "+f"(c[3])
        : "r"(a[0]), "r"(a[1]), "r"(a[2]), "r"(a[3]), "r"(b0), "r"(b1));
}

// one warp per input row: 32 lanes x float4 = 128 floats, fully coalesced
__global__ void __launch_bounds__(256)
norm_kernel(const float* __restrict__ x, const float* __restrict__ y) {
    int gw = (blockIdx.x * 256 + threadIdx.x) >> 5;
    int lane = threadIdx.x & 31;
    const float* src = (gw < 32768) ? (x + (size_t)gw * 128)
                                    : (y + (size_t)(gw - 32768) * 128);
    float4 v = *(const float4*)(src + lane * 4);
    float s = v.x * v.x + v.y * v.y + v.z * v.z + v.w * v.w;
#pragma unroll
    for (int o = 16; o; o >>= 1) s += __shfl_xor_sync(0xffffffffu, s, o);
    if (lane == 0) g_norms[gw] = s;
}

// 128x128 fp32 tile: global row-major (ld 128) -> smem padded (ld 132)
__device__ __forceinline__ void load_tile_async(uint32_t sdst, const float* __restrict__ g, int tid) {
#pragma unroll
    for (int i = 0; i < 8; ++i) {
        int idx = i * 512 + tid;
        int r = idx >> 5, c4 = idx & 31;
        cp_async16(sdst + (uint32_t)(r * LDK + c4 * 4) * 4u, g + r * 128 + c4 * 4);
    }
}

__global__ void __launch_bounds__(512, 1)
pairwise_cost_kernel(const float* __restrict__ x, const float* __restrict__ y,
                     float* __restrict__ out) {
    extern __shared__ char smem[];
    const uint32_t sb = smem_u32(smem);
    const int tid = threadIdx.x, lane = tid & 31, wid = tid >> 5;

    const int bxn = blockIdx.x;   // n-chunk (512 wide)
    const int bym = blockIdx.y;   // m tile (128 rows)
    const int bz  = blockIdx.z;   // batch

    const float* xg = x + ((size_t)(bz * 2048 + bym * 128)) * 128;
    const float* yg = y + ((size_t)(bz * 2048 + bxn * 512)) * 128;

    load_tile_async(sb + SM_X, xg, tid);               cp_commit();
    load_tile_async(sb + SM_Y0, yg, tid);              cp_commit();
    load_tile_async(sb + SM_Y1, yg + 128 * 128, tid);  cp_commit();

    // 16 warps: 4 m-groups x 4 n-groups, warp tile 32x32
    const int m0  = (wid >> 2) * 32;
    const int n0w = (wid & 3) * 32;

    // x norms (precomputed, L2-hit)
    float x2r[4];
#pragma unroll
    for (int mf = 0; mf < 2; ++mf)
#pragma unroll
        for (int e2 = 0; e2 < 2; ++e2)
            x2r[2 * mf + e2] =
                g_norms[bz * 2048 + bym * 128 + m0 + 16 * mf + (lane >> 2) + 8 * e2];

    // A ldmatrix base addresses (lanes 0-15: rows, 16-31: +16B for k+4)
    uint32_t baseA[2];
#pragma unroll
    for (int mf = 0; mf < 2; ++mf)
        baseA[mf] = sb + SM_X +
            ((uint32_t)((m0 + 16 * mf + (lane & 15)) * LDK) + ((lane & 16) >> 2)) * 4u;

    // B ldmatrix base offsets: lanes [0:8)=oct0/k-lo, [8:16)=oct0/k-hi,
    // [16:24)=oct1/k-lo, [24:32)=oct1/k-hi
    const uint32_t bn = (uint32_t)(n0w + ((lane >> 4) & 1) * 8 + (lane & 7));
    const uint32_t bk = (uint32_t)(((lane >> 3) & 1) * 4);
    uint32_t baseB[2];
    baseB[0] = (bn * LDK + bk) * 4u;
    baseB[1] = ((bn + 16) * LDK + bk) * 4u;

    cp_wait<2>();                 // x tile resident
    __syncthreads();

    float* og = out + (size_t)bz * 2048 * 2048;

#pragma unroll 1
    for (int t = 0; t < 4; ++t) {
        const uint32_t ybuf = (t & 1) ? SM_Y1 : SM_Y0;

        if (t < 3) cp_wait<1>(); else cp_wait<0>();   // y[t] resident
        __syncthreads();

        float c[2][4][4] = {};
#pragma unroll
        for (int kk = 0; kk < 16; ++kk) {
            uint32_t a[2][4], b[2][4];
#pragma unroll
            for (int mf = 0; mf < 2; ++mf)
                ldm_x4(a[mf], baseA[mf] + kk * 32u);
#pragma unroll
            for (int g = 0; g < 2; ++g)
                ldm_x4(b[g], sb + ybuf + baseB[g] + kk * 32u);
#pragma unroll
            for (int mf = 0; mf < 2; ++mf)
#pragma unroll
                for (int nf = 0; nf < 4; ++nf)
                    mma_tf32(c[mf][nf], a[mf],
                             b[nf >> 1][(nf & 1) * 2], b[nf >> 1][(nf & 1) * 2 + 1]);
        }

        // prefetch y[t+2] into the buffer we just finished reading
        if (t < 2) {
            __syncthreads();
            load_tile_async(sb + ybuf, yg + (size_t)(t + 2) * 128 * 128, tid);
            cp_commit();
        }

        // ---- fused epilogue: max(x2 + y2 - 2*d, 0) ----
        const int ncol = bxn * 512 + t * 128 + n0w;
        float2 y2f[4];
#pragma unroll
        for (int nf = 0; nf < 4; ++nf)
            y2f[nf] = *(const float2*)
                &g_norms[32768 + bz * 2048 + ncol + 8 * nf + 2 * (lane & 3)];

#pragma unroll
        for (int mf = 0; mf < 2; ++mf) {
#pragma unroll
            for (int e2 = 0; e2 < 2; ++e2) {
                int rowg = bym * 128 + m0 + 16 * mf + (lane >> 2) + 8 * e2;
                float xn = x2r[2 * mf + e2];
                float* orow = og + (size_t)rowg * 2048 + ncol;
#pragma unroll
                for (int nf = 0; nf < 4; ++nf) {
                    float2 o;
                    o.x = fmaxf(fmaf(-2.f, c[mf][nf][e2 * 2 + 0], xn + y2f[nf].x), 0.f);
                    o.y = fmaxf(fmaf(-2.f, c[mf][nf][e2 * 2 + 1], xn + y2f[nf].y), 0.f);
                    *(float2*)&orow[8 * nf + 2 * (lane & 3)] = o;
                }
            }
        }
    }
}

extern "C" void kernel_launch(void* const* d_in, const int* in_sizes, int n_in,
                              void* d_out, int out_size) {
    const float* x = (const float*)d_in[0];
    const float* y = (const float*)d_in[1];
    float* out = (float*)d_out;
    norm_kernel<<<8192, 256>>>(x, y);
    cudaFuncSetAttribute(pairwise_cost_kernel,
                         cudaFuncAttributeMaxDynamicSharedMemorySize, SMEM_TOTAL);
    dim3 grid(4, 16, 16);
    pairwise_cost_kernel<<<grid, 512, SMEM_TOTAL>>>(x, y, out);
}

// round 4
// speedup vs baseline: 1.0266x; 1.0266x over previous
#include <cuda_runtime.h>
#include <cstdint>

#define LDK 132                      // padded row pitch in floats (conflict-free, 16B-aligned rows)
#define TILE_B (128 * LDK * 4)       // 67584 bytes per 128x128 fp32 tile

#define SM_X   0
#define SM_Y0  TILE_B
#define SM_Y1  (2 * TILE_B)
#define SMEM_TOTAL (3 * TILE_B)

__device__ float g_norms[2 * 16 * 2048];   // [0,32768): ||x_row||^2, [32768,65536): ||y_row||^2

__device__ __forceinline__ uint32_t smem_u32(const void* p) {
    uint32_t a;
    asm("{ .reg .u64 t; cvta.to.shared.u64 t, %1; cvt.u32.u64 %0, t; }" : "=r"(a) : "l"(p));
    return a;
}
__device__ __forceinline__ void cp_async16(uint32_t dst, const float* src) {
    asm volatile("cp.async.cg.shared.global [%0], [%1], 16;" :: "r"(dst), "l"(src));
}
__device__ __forceinline__ void cp_commit() {
    asm volatile("cp.async.commit_group;" ::: "memory");
}
template <int N>
__device__ __forceinline__ void cp_wait() {
    asm volatile("cp.async.wait_group %0;" :: "n"(N) : "memory");
}
__device__ __forceinline__ void ldm_x4(uint32_t* r, uint32_t addr) {
    asm volatile("ldmatrix.sync.aligned.m8n8.x4.shared.b16 {%0,%1,%2,%3}, [%4];"
                 : "=r"(r[0]), "=r"(r[1]), "=r"(r[2]), "=r"(r[3]) : "r"(addr));
}
__device__ __forceinline__ void mma_tf32(float* c, const uint32_t* a, uint32_t b0, uint32_t b1) {
    asm volatile(
        "mma.sync.aligned.m16n8k8.row.col.f32.tf32.tf32.f32 "
        "{%0,%1,%2,%3},{%4,%5,%6,%7},{%8,%9},{%0,%1,%2,%3};"
        : "+f"(c[0]), "+f"(c[1]), "+f"(c[2]), "+f"(c[3])
        : "r"(a[0]), "r"(a[1]), "r"(a[2]), "r"(a[3]), "r"(b0), "r"(b1));
}

// one warp per input row: 32 lanes x float4 = 128 floats, fully coalesced
__global__ void __launch_bounds__(256)
norm_kernel(const float* __restrict__ x, const float* __restrict__ y) {
    int gw = (blockIdx.x * 256 + threadIdx.x) >> 5;
    int lane = threadIdx.x & 31;
    const float* src = (gw < 32768) ? (x + (size_t)gw * 128)
                                    : (y + (size_t)(gw - 32768) * 128);
    float4 v = *(const float4*)(src + lane * 4);
    float s = v.x * v.x + v.y * v.y + v.z * v.z + v.w * v.w;
#pragma unroll
    for (int o = 16; o; o >>= 1) s += __shfl_xor_sync(0xffffffffu, s, o);
    if (lane == 0) g_norms[gw] = s;
}

// 128x128 fp32 tile: global row-major (ld 128) -> smem padded (ld 132)
__device__ __forceinline__ void load_tile_async(uint32_t sdst, const float* __restrict__ g, int tid) {
#pragma unroll
    for (int i = 0; i < 16; ++i) {
        int idx = i * 256 + tid;
        int r = idx >> 5, c4 = idx & 31;
        cp_async16(sdst + (uint32_t)(r * LDK + c4 * 4) * 4u, g + r * 128 + c4 * 4);
    }
}

__global__ void __launch_bounds__(256, 1)
pairwise_cost_kernel(const float* __restrict__ x, const float* __restrict__ y,
                     float* __restrict__ out) {
    extern __shared__ char smem[];
    const uint32_t sb = smem_u32(smem);
    const int tid = threadIdx.x, lane = tid & 31, wid = tid >> 5;

    const int bxn = blockIdx.x;   // n-chunk (512 wide)
    const int bym = blockIdx.y;   // m tile (128 rows)
    const int bz  = blockIdx.z;   // batch

    const float* xg = x + ((size_t)(bz * 2048 + bym * 128)) * 128;
    const float* yg = y + ((size_t)(bz * 2048 + bxn * 512)) * 128;

    load_tile_async(sb + SM_X, xg, tid);               cp_commit();
    load_tile_async(sb + SM_Y0, yg, tid);              cp_commit();
    load_tile_async(sb + SM_Y1, yg + 128 * 128, tid);  cp_commit();

    // 8 warps: 2 m-groups x 4 n-groups, warp tile 64x32
    const int m0  = (wid >> 2) * 64;
    const int n0w = (wid & 3) * 32;

    // x norms (precomputed, L2-resident)
    float x2r[8];
#pragma unroll
    for (int mf = 0; mf < 4; ++mf)
#pragma unroll
        for (int e2 = 0; e2 < 2; ++e2)
            x2r[2 * mf + e2] =
                g_norms[bz * 2048 + bym * 128 + m0 + 16 * mf + (lane >> 2) + 8 * e2];

    // A ldmatrix base addresses (lanes 0-15: rows, 16-31: +16B for k+4)
    uint32_t baseA[4];
#pragma unroll
    for (int mf = 0; mf < 4; ++mf)
        baseA[mf] = sb + SM_X +
            ((uint32_t)((m0 + 16 * mf + (lane & 15)) * LDK) + ((lane & 16) >> 2)) * 4u;

    // B ldmatrix base offsets: lanes [0:8)=oct0/k-lo, [8:16)=oct0/k-hi,
    // [16:24)=oct1/k-lo, [24:32)=oct1/k-hi
    const uint32_t bn = (uint32_t)(n0w + ((lane >> 4) & 1) * 8 + (lane & 7));
    const uint32_t bk = (uint32_t)(((lane >> 3) & 1) * 4);
    uint32_t baseB[2];
    baseB[0] = (bn * LDK + bk) * 4u;
    baseB[1] = ((bn + 16) * LDK + bk) * 4u;

    cp_wait<2>();                 // x tile resident
    __syncthreads();

    float* og = out + (size_t)bz * 2048 * 2048;

#pragma unroll 1
    for (int t = 0; t < 4; ++t) {
        const uint32_t ybuf = (t & 1) ? SM_Y1 : SM_Y0;

        if (t < 3) cp_wait<1>(); else cp_wait<0>();   // y[t] resident
        __syncthreads();

        // ---- MMA mainloop, 2-stage software-pipelined fragments ----
        float c[4][4][4] = {};
        uint32_t afr[2][4][4], bfr[2][2][4];

#pragma unroll
        for (int mf = 0; mf < 4; ++mf) ldm_x4(afr[0][mf], baseA[mf]);
#pragma unroll
        for (int g = 0; g < 2; ++g)    ldm_x4(bfr[0][g], sb + ybuf + baseB[g]);

#pragma unroll
        for (int kk = 0; kk < 16; ++kk) {
            const int cur = kk & 1, nxt = cur ^ 1;
            if (kk < 15) {
                // issue next-k fragment loads BEFORE consuming current ones
#pragma unroll
                for (int mf = 0; mf < 4; ++mf)
                    ldm_x4(afr[nxt][mf], baseA[mf] + (kk + 1) * 32u);
#pragma unroll
                for (int g = 0; g < 2; ++g)
                    ldm_x4(bfr[nxt][g], sb + ybuf + baseB[g] + (kk + 1) * 32u);
            }
#pragma unroll
            for (int mf = 0; mf < 4; ++mf)
#pragma unroll
                for (int nf = 0; nf < 4; ++nf)
                    mma_tf32(c[mf][nf], afr[cur][mf],
                             bfr[cur][nf >> 1][(nf & 1) * 2],
                             bfr[cur][nf >> 1][(nf & 1) * 2 + 1]);
        }

        // prefetch y[t+2] into the buffer we just finished reading
        if (t < 2) {
            __syncthreads();
            load_tile_async(sb + ybuf, yg + (size_t)(t + 2) * 128 * 128, tid);
            cp_commit();
        }

        // ---- fused epilogue: max(x2 + y2 - 2*d, 0) ----
        const int ncol = bxn * 512 + t * 128 + n0w;
        float2 y2f[4];
#pragma unroll
        for (int nf = 0; nf < 4; ++nf)
            y2f[nf] = *(const float2*)
                &g_norms[32768 + bz * 2048 + ncol + 8 * nf + 2 * (lane & 3)];

#pragma unroll
        for (int mf = 0; mf < 4; ++mf) {
#pragma unroll
            for (int e2 = 0; e2 < 2; ++e2) {
                int rowg = bym * 128 + m0 + 16 * mf + (lane >> 2) + 8 * e2;
                float xn = x2r[2 * mf + e2];
                float* orow = og + (size_t)rowg * 2048 + ncol;
#pragma unroll
                for (int nf = 0; nf < 4; ++nf) {
                    float2 o;
                    o.x = fmaxf(fmaf(-2.f, c[mf][nf][e2 * 2 + 0], xn + y2f[nf].x), 0.f);
                    o.y = fmaxf(fmaf(-2.f, c[mf][nf][e2 * 2 + 1], xn + y2f[nf].y), 0.f);
                    *(float2*)&orow[8 * nf + 2 * (lane & 3)] = o;
                }
            }
        }
    }
}

extern "C" void kernel_launch(void* const* d_in, const int* in_sizes, int n_in,
                              void* d_out, int out_size) {
    const float* x = (const float*)d_in[0];
    const float* y = (const float*)d_in[1];
    float* out = (float*)d_out;
    norm_kernel<<<8192, 256>>>(x, y);
    cudaFuncSetAttribute(pairwise_cost_kernel,
                         cudaFuncAttributeMaxDynamicSharedMemorySize, SMEM_TOTAL);
    dim3 grid(4, 16, 16);
    pairwise_cost_kernel<<<grid, 256, SMEM_TOTAL>>>(x, y, out);
}

// round 5
// speedup vs baseline: 1.3832x; 1.3473x over previous
#include <cuda_runtime.h>
#include <cuda_bf16.h>
#include <cstdint>

#define KAUG   144                   // augmented K (bf16 elems), dense global pitch
#define PITCH  304                   // smem row pitch bytes (152 bf16): banks 12-apart, 16B-aligned
#define TILE_B (128 * PITCH)         // 38912 B per 128-row tile

#define SM_X   0
#define SM_Y0  TILE_B
#define SM_Y1  (2 * TILE_B)
#define SMEM_TOTAL (3 * TILE_B)

// augmented bf16 copies: row layout [128 payload | 4 aug | 12 zeros]
__device__ __nv_bfloat16 g_xa[32768 * KAUG];
__device__ __nv_bfloat16 g_ya[32768 * KAUG];

__device__ __forceinline__ uint32_t smem_u32(const void* p) {
    uint32_t a;
    asm("{ .reg .u64 t; cvta.to.shared.u64 t, %1; cvt.u32.u64 %0, t; }" : "=r"(a) : "l"(p));
    return a;
}
__device__ __forceinline__ void cp_async16(uint32_t dst, const void* src) {
    asm volatile("cp.async.cg.shared.global [%0], [%1], 16;" :: "r"(dst), "l"(src));
}
__device__ __forceinline__ void cp_commit() {
    asm volatile("cp.async.commit_group;" ::: "memory");
}
template <int N>
__device__ __forceinline__ void cp_wait() {
    asm volatile("cp.async.wait_group %0;" :: "n"(N) : "memory");
}
__device__ __forceinline__ void ldm_x4(uint32_t* r, uint32_t addr) {
    asm volatile("ldmatrix.sync.aligned.m8n8.x4.shared.b16 {%0,%1,%2,%3}, [%4];"
                 : "=r"(r[0]), "=r"(r[1]), "=r"(r[2]), "=r"(r[3]) : "r"(addr));
}
__device__ __forceinline__ void mma_bf16(float* c, const uint32_t* a, uint32_t b0, uint32_t b1) {
    asm volatile(
        "mma.sync.aligned.m16n8k16.row.col.f32.bf16.bf16.f32 "
        "{%0,%1,%2,%3},{%4,%5,%6,%7},{%8,%9},{%0,%1,%2,%3};"
        : "+f"(c[0]), "+f"(c[1]), "+f"(c[2]), "+f"(c[3])
        : "r"(a[0]), "r"(a[1]), "r"(a[2]), "r"(a[3]), "r"(b0), "r"(b1));
}

// One warp per input row: build augmented bf16 row.
// x rows: [-2x | x2h x2l 1 1 | 0...]    y rows: [y | 1 1 y2h y2l | 0...]
__global__ void __launch_bounds__(256)
prep_kernel(const float* __restrict__ x, const float* __restrict__ y) {
    int gw = (blockIdx.x * 256 + threadIdx.x) >> 5;
    int lane = threadIdx.x & 31;
    bool isx = gw < 32768;
    int row = isx ? gw : gw - 32768;
    const float* src = (isx ? x : y) + (size_t)row * 128;
    __nv_bfloat16* dst = (isx ? g_xa : g_ya) + (size_t)row * KAUG;

    float4 v = *(const float4*)(src + lane * 4);
    float s = v.x * v.x + v.y * v.y + v.z * v.z + v.w * v.w;
#pragma unroll
    for (int o = 16; o; o >>= 1) s += __shfl_xor_sync(0xffffffffu, s, o);

    float sc = isx ? -2.0f : 1.0f;
    __nv_bfloat162* d2 = (__nv_bfloat162*)(dst + lane * 4);
    d2[0] = __nv_bfloat162(__float2bfloat16(v.x * sc), __float2bfloat16(v.y * sc));
    d2[1] = __nv_bfloat162(__float2bfloat16(v.z * sc), __float2bfloat16(v.w * sc));

    if (lane == 0) {
        __nv_bfloat16 h = __float2bfloat16(s);
        __nv_bfloat16 l = __float2bfloat16(s - __bfloat162float(h));
        __nv_bfloat16 one = __float2bfloat16(1.0f);
        __nv_bfloat16 zero = __float2bfloat16(0.0f);
        if (isx) {
            dst[128] = h; dst[129] = l; dst[130] = one; dst[131] = one;
        } else {
            dst[128] = one; dst[129] = one; dst[130] = h; dst[131] = l;
        }
#pragma unroll
        for (int c = 132; c < 144; ++c) dst[c] = zero;
    }
}

// 128-row bf16 tile: global dense (288B rows) -> smem padded (304B rows)
__device__ __forceinline__ void load_tile_async(uint32_t sdst, const __nv_bfloat16* __restrict__ g,
                                                int tid) {
    const char* gb = (const char*)g;
#pragma unroll
    for (int i = 0; i < 9; ++i) {
        int idx = i * 256 + tid;          // 2304 chunks of 16B
        int r = idx / 18, c = idx - r * 18;
        cp_async16(sdst + (uint32_t)(r * PITCH + c * 16), gb + (size_t)idx * 16);
    }
}

__global__ void __launch_bounds__(256, 1)
pairwise_cost_kernel(float* __restrict__ out) {
    extern __shared__ char smem[];
    const uint32_t sb = smem_u32(smem);
    const int tid = threadIdx.x, lane = tid & 31, wid = tid >> 5;

    const int bxn = blockIdx.x;   // n-chunk (512 wide)
    const int bym = blockIdx.y;   // m tile (128 rows)
    const int bz  = blockIdx.z;   // batch

    const __nv_bfloat16* xg = g_xa + (size_t)(bz * 2048 + bym * 128) * KAUG;
    const __nv_bfloat16* yg = g_ya + (size_t)(bz * 2048 + bxn * 512) * KAUG;

    load_tile_async(sb + SM_X, xg, tid);                cp_commit();
    load_tile_async(sb + SM_Y0, yg, tid);               cp_commit();
    load_tile_async(sb + SM_Y1, yg + 128 * KAUG, tid);  cp_commit();

    // 8 warps: 2 m-groups x 4 n-groups, warp tile 64x32
    const int m0  = (wid >> 2) * 64;
    const int n0w = (wid & 3) * 32;

    // A ldmatrix: lanes 0-15 -> rows, lanes 16-31 -> +16B (k8-15)
    uint32_t baseA[4];
#pragma unroll
    for (int mf = 0; mf < 4; ++mf)
        baseA[mf] = sb + SM_X + (uint32_t)((m0 + 16 * mf + (lane & 15)) * PITCH)
                  + ((lane & 16) ? 16u : 0u);

    // B ldmatrix: octets -> {n0-7,k0},{n0-7,k8},{n8-15,k0},{n8-15,k8}
    const uint32_t bnr = (uint32_t)(n0w + ((lane >> 4) & 1) * 8 + (lane & 7));
    const uint32_t bkb = ((lane >> 3) & 1) * 16u;
    uint32_t baseB[2];
    baseB[0] = bnr * PITCH + bkb;
    baseB[1] = (bnr + 16) * PITCH + bkb;

    cp_wait<2>();                 // x tile resident
    __syncthreads();

    float* og = out + (size_t)bz * 2048 * 2048;

#pragma unroll 1
    for (int t = 0; t < 4; ++t) {
        const uint32_t ybuf = (t & 1) ? SM_Y1 : SM_Y0;

        if (t < 3) cp_wait<1>(); else cp_wait<0>();   // y[t] resident
        __syncthreads();

        // ---- MMA mainloop: 9 k16-steps, 2-stage fragment pipeline ----
        float c[4][4][4] = {};
        uint32_t afr[2][4][4], bfr[2][2][4];

#pragma unroll
        for (int mf = 0; mf < 4; ++mf) ldm_x4(afr[0][mf], baseA[mf]);
#pragma unroll
        for (int g = 0; g < 2; ++g)    ldm_x4(bfr[0][g], sb + ybuf + baseB[g]);

#pragma unroll
        for (int kk = 0; kk < 9; ++kk) {
            const int cur = kk & 1, nxt = cur ^ 1;
            if (kk < 8) {
#pragma unroll
                for (int mf = 0; mf < 4; ++mf)
                    ldm_x4(afr[nxt][mf], baseA[mf] + (kk + 1) * 32u);
#pragma unroll
                for (int g = 0; g < 2; ++g)
                    ldm_x4(bfr[nxt][g], sb + ybuf + baseB[g] + (kk + 1) * 32u);
            }
#pragma unroll
            for (int mf = 0; mf < 4; ++mf)
#pragma unroll
                for (int nf = 0; nf < 4; ++nf)
                    mma_bf16(c[mf][nf], afr[cur][mf],
                             bfr[cur][nf >> 1][(nf & 1) * 2],
                             bfr[cur][nf >> 1][(nf & 1) * 2 + 1]);
        }

        // prefetch y[t+2] into the buffer we just finished reading
        if (t < 2) {
            __syncthreads();
            load_tile_async(sb + ybuf, yg + (size_t)(t + 2) * 128 * KAUG, tid);
            cp_commit();
        }

        // ---- epilogue: D already equals cost; just clamp and store ----
        const int ncol = bxn * 512 + t * 128 + n0w;
#pragma unroll
        for (int mf = 0; mf < 4; ++mf) {
#pragma unroll
            for (int e2 = 0; e2 < 2; ++e2) {
                int rowg = bym * 128 + m0 + 16 * mf + (lane >> 2) + 8 * e2;
                float* orow = og + (size_t)rowg * 2048 + ncol;
#pragma unroll
                for (int nf = 0; nf < 4; ++nf) {
                    float2 o;
                    o.x = fmaxf(c[mf][nf][e2 * 2 + 0], 0.f);
                    o.y = fmaxf(c[mf][nf][e2 * 2 + 1], 0.f);
                    *(float2*)&orow[8 * nf + 2 * (lane & 3)] = o;
                }
            }
        }
    }
}

extern "C" void kernel_launch(void* const* d_in, const int* in_sizes, int n_in,
                              void* d_out, int out_size) {
    const float* x = (const float*)d_in[0];
    const float* y = (const float*)d_in[1];
    float* out = (float*)d_out;
    prep_kernel<<<8192, 256>>>(x, y);
    cudaFuncSetAttribute(pairwise_cost_kernel,
                         cudaFuncAttributeMaxDynamicSharedMemorySize, SMEM_TOTAL);
    dim3 grid(4, 16, 16);
    pairwise_cost_kernel<<<grid, 256, SMEM_TOTAL>>>(out);
}

// round 6
// speedup vs baseline: 1.7132x; 1.2386x over previous
#include <cuda_runtime.h>
#include <cuda_bf16.h>
#include <cstdint>

#define KAUG   136                   // 128 payload + 4 aug + 4 zeros (bf16)
#define PITCH  272                   // bytes/row: 17x16B, conflict-free (68 words = 4 banks)
#define TILE_B (128 * PITCH)         // 34816 B per 128-row tile
#define CHUNKS (128 * 17)            // 16B chunks per tile = 2176

#define SM_X   0
#define SM_Y0  TILE_B
#define SM_Y1  (2 * TILE_B)
#define SMEM_TOTAL (3 * TILE_B)      // 104448 B -> 2 CTAs/SM

// augmented bf16 copies, dense pitch KAUG
__device__ __nv_bfloat16 g_xa[32768 * KAUG];
__device__ __nv_bfloat16 g_ya[32768 * KAUG];

__device__ __forceinline__ uint32_t smem_u32(const void* p) {
    uint32_t a;
    asm("{ .reg .u64 t; cvta.to.shared.u64 t, %1; cvt.u32.u64 %0, t; }" : "=r"(a) : "l"(p));
    return a;
}
__device__ __forceinline__ void cp_async16(uint32_t dst, const void* src) {
    asm volatile("cp.async.cg.shared.global [%0], [%1], 16;" :: "r"(dst), "l"(src));
}
__device__ __forceinline__ void cp_commit() {
    asm volatile("cp.async.commit_group;" ::: "memory");
}
template <int N>
__device__ __forceinline__ void cp_wait() {
    asm volatile("cp.async.wait_group %0;" :: "n"(N) : "memory");
}
__device__ __forceinline__ void ldm_x4(uint32_t* r, uint32_t addr) {
    asm volatile("ldmatrix.sync.aligned.m8n8.x4.shared.b16 {%0,%1,%2,%3}, [%4];"
                 : "=r"(r[0]), "=r"(r[1]), "=r"(r[2]), "=r"(r[3]) : "r"(addr));
}
__device__ __forceinline__ void ldm_x2(uint32_t* r, uint32_t addr) {
    asm volatile("ldmatrix.sync.aligned.m8n8.x2.shared.b16 {%0,%1}, [%2];"
                 : "=r"(r[0]), "=r"(r[1]) : "r"(addr));
}
__device__ __forceinline__ void mma_bf16(float* c, const uint32_t* a, uint32_t b0, uint32_t b1) {
    asm volatile(
        "mma.sync.aligned.m16n8k16.row.col.f32.bf16.bf16.f32 "
        "{%0,%1,%2,%3},{%4,%5,%6,%7},{%8,%9},{%0,%1,%2,%3};"
        : "+f"(c[0]), "+f"(c[1]), "+f"(c[2]), "+f"(c[3])
        : "r"(a[0]), "r"(a[1]), "r"(a[2]), "r"(a[3]), "r"(b0), "r"(b1));
}
__device__ __forceinline__ void mma_bf16_k8(float* c, uint32_t a0, uint32_t a1, uint32_t b0) {
    asm volatile(
        "mma.sync.aligned.m16n8k8.row.col.f32.bf16.bf16.f32 "
        "{%0,%1,%2,%3},{%4,%5},{%6},{%0,%1,%2,%3};"
        : "+f"(c[0]), "+f"(c[1]), "+f"(c[2]), "+f"(c[3])
        : "r"(a0), "r"(a1), "r"(b0));
}

// One warp per input row: build augmented bf16 row.
// x rows: [-2x | x2h x2l 1 1 | 0 0 0 0]   y rows: [y | 1 1 y2h y2l | 0 0 0 0]
__global__ void __launch_bounds__(256)
prep_kernel(const float* __restrict__ x, const float* __restrict__ y) {
    int gw = (blockIdx.x * 256 + threadIdx.x) >> 5;
    int lane = threadIdx.x & 31;
    bool isx = gw < 32768;
    int row = isx ? gw : gw - 32768;
    const float* src = (isx ? x : y) + (size_t)row * 128;
    __nv_bfloat16* dst = (isx ? g_xa : g_ya) + (size_t)row * KAUG;

    float4 v = *(const float4*)(src + lane * 4);
    float s = v.x * v.x + v.y * v.y + v.z * v.z + v.w * v.w;
#pragma unroll
    for (int o = 16; o; o >>= 1) s += __shfl_xor_sync(0xffffffffu, s, o);

    float sc = isx ? -2.0f : 1.0f;
    __nv_bfloat162 p0(__float2bfloat16(v.x * sc), __float2bfloat16(v.y * sc));
    __nv_bfloat162 p1(__float2bfloat16(v.z * sc), __float2bfloat16(v.w * sc));
    uint2 pk;
    pk.x = *(uint32_t*)&p0;
    pk.y = *(uint32_t*)&p1;
    *(uint2*)(dst + lane * 4) = pk;

    if (lane == 0) {
        __nv_bfloat16 h = __float2bfloat16(s);
        __nv_bfloat16 l = __float2bfloat16(s - __bfloat162float(h));
        __nv_bfloat16 one = __float2bfloat16(1.0f);
        __nv_bfloat162 hl(h, l), oo(one, one);
        uint4 tail;
        if (isx) { tail.x = *(uint32_t*)&hl; tail.y = *(uint32_t*)&oo; }
        else     { tail.x = *(uint32_t*)&oo; tail.y = *(uint32_t*)&hl; }
        tail.z = 0u; tail.w = 0u;
        *(uint4*)(dst + 128) = tail;
    }
}

// 128-row bf16 tile: global dense (272B rows) -> smem (272B pitch)
__device__ __forceinline__ void load_tile_async(uint32_t sdst, const __nv_bfloat16* __restrict__ g,
                                                int tid) {
    const char* gb = (const char*)g;
#pragma unroll
    for (int i = 0; i < 9; ++i) {
        int idx = i * 256 + tid;
        if (idx < CHUNKS)
            cp_async16(sdst + (uint32_t)idx * 16u, gb + (size_t)idx * 16);
    }
}

__global__ void __launch_bounds__(256, 2)
pairwise_cost_kernel(float* __restrict__ out) {
    extern __shared__ char smem[];
    const uint32_t sb = smem_u32(smem);
    const int tid = threadIdx.x, lane = tid & 31, wid = tid >> 5;

    const int bym = blockIdx.x;   // m tile (128 rows) — fastest: co-resident CTAs share y
    const int bxn = blockIdx.y;   // n-chunk (512 wide)
    const int bz  = blockIdx.z;   // batch

    const __nv_bfloat16* xg = g_xa + (size_t)(bz * 2048 + bym * 128) * KAUG;
    const __nv_bfloat16* yg = g_ya + (size_t)(bz * 2048 + bxn * 512) * KAUG;

    load_tile_async(sb + SM_X, xg, tid);                cp_commit();
    load_tile_async(sb + SM_Y0, yg, tid);               cp_commit();
    load_tile_async(sb + SM_Y1, yg + 128 * KAUG, tid);  cp_commit();

    // 8 warps: 2 m-groups x 4 n-groups, warp tile 64x32
    const int m0  = (wid >> 2) * 64;
    const int n0w = (wid & 3) * 32;

    // A ldmatrix: lanes 0-15 -> rows, lanes 16-31 -> +16B (k8-15)
    uint32_t baseA[4];
#pragma unroll
    for (int mf = 0; mf < 4; ++mf)
        baseA[mf] = sb + SM_X + (uint32_t)((m0 + 16 * mf + (lane & 15)) * PITCH)
                  + ((lane & 16) ? 16u : 0u);

    // B ldmatrix (k16 steps): octets -> {n0-7,klo},{n0-7,khi},{n8-15,klo},{n8-15,khi}
    const uint32_t bnr = (uint32_t)(n0w + ((lane >> 4) & 1) * 8 + (lane & 7));
    const uint32_t bkb = ((lane >> 3) & 1) * 16u;
    uint32_t baseB[2];
    baseB[0] = bnr * PITCH + bkb;
    baseB[1] = (bnr + 16) * PITCH + bkb;

    // tail (k8) addresses: A rows (lanes 0-15), B 4 n8-octets, both at +256B (k=128..135)
    const uint32_t tailB = (uint32_t)((n0w + ((lane >> 3) & 3) * 8 + (lane & 7)) * PITCH) + 256u;

    cp_wait<2>();                 // x tile resident
    __syncthreads();

    float* og = out + (size_t)bz * 2048 * 2048;

#pragma unroll 1
    for (int t = 0; t < 4; ++t) {
        const uint32_t ybuf = (t & 1) ? SM_Y1 : SM_Y0;

        if (t < 3) cp_wait<1>(); else cp_wait<0>();   // y[t] resident
        __syncthreads();

        float c[4][4][4] = {};

        // ---- 8 full k16 steps ----
#pragma unroll
        for (int kk = 0; kk < 8; ++kk) {
            uint32_t a[4][4], b[2][4];
#pragma unroll
            for (int mf = 0; mf < 4; ++mf) ldm_x4(a[mf], baseA[mf] + kk * 32u);
#pragma unroll
            for (int g = 0; g < 2; ++g)    ldm_x4(b[g], sb + ybuf + baseB[g] + kk * 32u);
#pragma unroll
            for (int mf = 0; mf < 4; ++mf)
#pragma unroll
                for (int nf = 0; nf < 4; ++nf)
                    mma_bf16(c[mf][nf], a[mf],
                             b[nf >> 1][(nf & 1) * 2], b[nf >> 1][(nf & 1) * 2 + 1]);
        }

        // ---- k8 tail (aug columns 128..135) ----
        {
            uint32_t at[4][2], bt[4];
            ldm_x4(bt, sb + ybuf + tailB);
#pragma unroll
            for (int mf = 0; mf < 4; ++mf)
                ldm_x2(at[mf], sb + SM_X +
                       (uint32_t)((m0 + 16 * mf + (lane & 15)) * PITCH) + 256u);
#pragma unroll
            for (int mf = 0; mf < 4; ++mf)
#pragma unroll
                for (int nf = 0; nf < 4; ++nf)
                    mma_bf16_k8(c[mf][nf], at[mf][0], at[mf][1], bt[nf]);
        }

        // prefetch y[t+2] into the buffer we just finished reading
        if (t < 2) {
            __syncthreads();
            load_tile_async(sb + ybuf, yg + (size_t)(t + 2) * 128 * KAUG, tid);
            cp_commit();
        }

        // ---- epilogue: D already equals cost; clamp and store ----
        const int ncol = bxn * 512 + t * 128 + n0w;
#pragma unroll
        for (int mf = 0; mf < 4; ++mf) {
#pragma unroll
            for (int e2 = 0; e2 < 2; ++e2) {
                int rowg = bym * 128 + m0 + 16 * mf + (lane >> 2) + 8 * e2;
                float* orow = og + (size_t)rowg * 2048 + ncol;
#pragma unroll
                for (int nf = 0; nf < 4; ++nf) {
                    float2 o;
                    o.x = fmaxf(c[mf][nf][e2 * 2 + 0], 0.f);
                    o.y = fmaxf(c[mf][nf][e2 * 2 + 1], 0.f);
                    *(float2*)&orow[8 * nf + 2 * (lane & 3)] = o;
                }
            }
        }
    }
}

extern "C" void kernel_launch(void* const* d_in, const int* in_sizes, int n_in,
                              void* d_out, int out_size) {
    const float* x = (const float*)d_in[0];
    const float* y = (const float*)d_in[1];
    float* out = (float*)d_out;
    prep_kernel<<<8192, 256>>>(x, y);
    cudaFuncSetAttribute(pairwise_cost_kernel,
                         cudaFuncAttributeMaxDynamicSharedMemorySize, SMEM_TOTAL);
    dim3 grid(16, 4, 16);   // bym fastest: co-resident CTAs share the same y chunk
    pairwise_cost_kernel<<<grid, 256, SMEM_TOTAL>>>(out);
}